// round 9
// baseline (speedup 1.0000x reference)
#include <cuda_runtime.h>
#include <math.h>

#define BATCH 8
#define NV 2048
#define NP 4096
#define DIM 64
#define S1_BLOCKS 512
#define S2_BLOCKS 512

// ---------------- scratch (device globals; no allocation) ----------------
__device__ float g_pf_unit[BATCH * NP * DIM];
__device__ float g_vf_unit[BATCH * NV * DIM];
__device__ float g_vm[BATCH * NV];
__device__ float g_flow[BATCH * NV * 3];
__device__ int   g_invis_list[BATCH * NV];
__device__ int   g_vis_list[BATCH * NV];
__device__ int   g_invis_cnt[BATCH];
__device__ int   g_vis_cnt[BATCH];
__device__ int   g_s2idx[BATCH * NV * 8];

// ---------------- f32x2 helpers ----------------
__device__ __forceinline__ void fma2(unsigned long long& d, unsigned long long a,
                                     unsigned long long b) {
    asm("fma.rn.f32x2 %0, %1, %2, %0;" : "+l"(d) : "l"(a), "l"(b));
}
__device__ __forceinline__ unsigned long long add2(unsigned long long a, unsigned long long b) {
    unsigned long long d;
    asm("add.rn.f32x2 %0, %1, %2;" : "=l"(d) : "l"(a), "l"(b));
    return d;
}
__device__ __forceinline__ float f2sum(unsigned long long a) {
    return __uint_as_float((unsigned)a) + __uint_as_float((unsigned)(a >> 32));
}

// ---------------- buffered top-8 ----------------
struct TopK {
    float v[8];   // ascending, v[0] = current 8th value (threshold)
    int id[8];
    float bv0, bv1;
    int bi0, bi1;
    int bcnt;
};

__device__ __forceinline__ void tk_init(TopK& t) {
#pragma unroll
    for (int j = 0; j < 8; j++) { t.v[j] = -1e30f; t.id[j] = -1; }
    t.bv0 = -1e30f;
    t.bv1 = -1e30f;
    t.bi0 = -1;
    t.bi1 = -1;
    t.bcnt = 0;
}

__device__ __forceinline__ void tk_insert(TopK& t, float s, int sid, bool c) {
    t.v[0] = c ? s : t.v[0];
    t.id[0] = c ? sid : t.id[0];
#pragma unroll
    for (int j = 0; j < 7; j++) {
        const bool g = t.v[j] > t.v[j + 1];
        const float lo = fminf(t.v[j], t.v[j + 1]);
        const float hi = fmaxf(t.v[j], t.v[j + 1]);
        const int tlo = g ? t.id[j + 1] : t.id[j];
        const int thi = g ? t.id[j] : t.id[j + 1];
        t.v[j] = lo;
        t.v[j + 1] = hi;
        t.id[j] = tlo;
        t.id[j + 1] = thi;
    }
}

__device__ __forceinline__ void tk_flush(TopK& t) {
    tk_insert(t, t.bv0, t.bi0, (t.bcnt >= 1) && (t.bv0 > t.v[0]));
    tk_insert(t, t.bv1, t.bi1, (t.bcnt >= 2) && (t.bv1 > t.v[0]));
    t.bcnt = 0;
}

// push one candidate per lane; flush (rare) when any lane's 2-slot buffer fills
__device__ __forceinline__ void tk_push(TopK& t, float s, int kid) {
    const bool c = s > t.v[0];
    const bool at0 = c & (t.bcnt == 0);
    const bool at1 = c & (t.bcnt == 1);
    t.bv0 = at0 ? s : t.bv0;
    t.bi0 = at0 ? kid : t.bi0;
    t.bv1 = at1 ? s : t.bv1;
    t.bi1 = at1 ? kid : t.bi1;
    t.bcnt += (int)c;
    if (__ballot_sync(0xffffffffu, t.bcnt >= 2)) tk_flush(t);
}

// ---------------- kernel A: vm + visibility compaction ----------------
__global__ void vm_kernel(const float* __restrict__ logits) {
    const int b = blockIdx.x;
    __shared__ float sv[NV];
    __shared__ float smin[256];
    __shared__ float smax[256];
    __shared__ int c_inv, c_vis;
    float lmin = 1e30f, lmax = -1e30f;
    for (int i = threadIdx.x; i < NV; i += 256) {
        float s = 1.0f / (1.0f + expf(-logits[b * NV + i]));
        sv[i] = s;
        lmin = fminf(lmin, s);
        lmax = fmaxf(lmax, s);
    }
    smin[threadIdx.x] = lmin;
    smax[threadIdx.x] = lmax;
    if (threadIdx.x == 0) { c_inv = 0; c_vis = 0; }
    __syncthreads();
    for (int off = 128; off > 0; off >>= 1) {
        if (threadIdx.x < off) {
            smin[threadIdx.x] = fminf(smin[threadIdx.x], smin[threadIdx.x + off]);
            smax[threadIdx.x] = fmaxf(smax[threadIdx.x], smax[threadIdx.x + off]);
        }
        __syncthreads();
    }
    const float mn = smin[0];
    const float inv = 1.0f / (smax[0] - mn);
    for (int i = threadIdx.x; i < NV; i += 256) {
        float v = (sv[i] - mn) * inv;
        g_vm[b * NV + i] = v;
        if (v >= 0.5f) {
            int p = atomicAdd(&c_vis, 1);
            g_vis_list[b * NV + p] = i;
        } else {
            int p = atomicAdd(&c_inv, 1);
            g_invis_list[b * NV + p] = i;
        }
    }
    __syncthreads();
    if (threadIdx.x == 0) {
        g_vis_cnt[b] = c_vis;
        g_invis_cnt[b] = c_inv;
    }
}

// ---------------- kernel B: unit-normalize key features ----------------
__global__ void norm_kernel(const float* __restrict__ vf, const float* __restrict__ pf) {
    const int gw = (blockIdx.x * blockDim.x + threadIdx.x) >> 5;
    const int lane = threadIdx.x & 31;
    const int totalRows = BATCH * NV + BATCH * NP;
    if (gw >= totalRows) return;
    const float* src;
    float* dst;
    if (gw < BATCH * NV) {
        src = vf + (size_t)gw * DIM;
        dst = g_vf_unit + (size_t)gw * DIM;
    } else {
        const int r = gw - BATCH * NV;
        src = pf + (size_t)r * DIM;
        dst = g_pf_unit + (size_t)r * DIM;
    }
    float2 v = ((const float2*)src)[lane];
    float ss = v.x * v.x + v.y * v.y;
#pragma unroll
    for (int o = 16; o > 0; o >>= 1) ss += __shfl_xor_sync(0xffffffffu, ss, o);
    const float inv = 1.0f / fmaxf(sqrtf(ss), 1e-12f);
    float2 o2;
    o2.x = v.x * inv;
    o2.y = v.y * inv;
    ((float2*)dst)[lane] = o2;
}

// 2-key dot over a 16-key tile with buffered top-8 maintenance
__device__ __forceinline__ void scan_tile(const ulonglong2 (*tileW)[16],
                                          const unsigned long long (&q2)[32],
                                          TopK& t, int idBase, const int* sid,
                                          int validLimit) {
#pragma unroll
    for (int k = 0; k < 16; k += 2) {
        unsigned long long a0 = 0ull, a1 = 0ull, b0 = 0ull, b1 = 0ull;
#pragma unroll
        for (int d = 0; d < 16; d++) {
            const ulonglong2 kva = tileW[k][d];
            const ulonglong2 kvb = tileW[k + 1][d];
            fma2(a0, q2[2 * d], kva.x);
            fma2(a1, q2[2 * d + 1], kva.y);
            fma2(b0, q2[2 * d], kvb.x);
            fma2(b1, q2[2 * d + 1], kvb.y);
        }
        float sA = f2sum(add2(a0, a1));
        float sB = f2sum(add2(b0, b1));
        sA = (k < validLimit) ? sA : -1e30f;
        sB = (k + 1 < validLimit) ? sB : -1e30f;
        tk_push(t, sA, sid ? sid[k] : (idBase + k));
        tk_push(t, sB, sid ? sid[k + 1] : (idBase + k + 1));
    }
}

// ---------------- fused kernel: stage1 (full) + stage2 KNN scan ----------------
__global__ __launch_bounds__(128, 4) void fused_kernel(
    const float* __restrict__ vtx, const float* __restrict__ pts,
    const float* __restrict__ vf_raw, const float* __restrict__ pf_raw,
    float* __restrict__ out) {
    const int tid = threadIdx.x;
    const int w = tid >> 5;
    const int lane = tid & 31;

    __shared__ ulonglong2 tile[4][16][16];  // 16 KB
    __shared__ float mval[32][32];          //  4 KB
    __shared__ int midx[32][32];            //  4 KB

    TopK t;
    tk_init(t);

    if (blockIdx.x < S1_BLOCKS) {
        // ================= stage 1 =================
        const int qg = blockIdx.x * 32 + lane;
        const int b = qg >> 11;

        unsigned long long q2[32];
        {
            const ulonglong2* qr = (const ulonglong2*)(vf_raw + (size_t)qg * DIM);
#pragma unroll
            for (int i = 0; i < 16; i++) {
                ulonglong2 t2 = qr[i];
                q2[2 * i] = t2.x;
                q2[2 * i + 1] = t2.y;
            }
        }

        const ulonglong2* pfU = (const ulonglong2*)(g_pf_unit + (size_t)b * NP * DIM);
        const int chunkBase = w * 1024;

        for (int tt = 0; tt < 64; tt++) {
            const int keyBase = chunkBase + tt * 16;
            const ulonglong2* src = pfU + (size_t)keyBase * 16;
            ulonglong2* dstT = &tile[w][0][0];
#pragma unroll
            for (int i = 0; i < 8; i++) dstT[lane + i * 32] = src[lane + i * 32];
            __syncwarp();
            scan_tile(tile[w], q2, t, keyBase, nullptr, 16);
            __syncwarp();
        }
        tk_flush(t);

#pragma unroll
        for (int j = 0; j < 8; j++) {
            mval[w * 8 + j][lane] = t.v[j];
            midx[w * 8 + j][lane] = t.id[j];
        }
        __syncthreads();

        if (w == 0) {
            TopK m;
            tk_init(m);
            for (int c = 0; c < 32; c++) tk_push(m, mval[c][lane], midx[c][lane]);
            tk_flush(m);

            const float vx = vtx[qg * 3 + 0];
            const float vy = vtx[qg * 3 + 1];
            const float vz = vtx[qg * 3 + 2];
            float n0 = 0.f, n1 = 0.f, n2 = 0.f, den = 0.f;
#pragma unroll
            for (int j = 0; j < 8; j++) {
                const int gp = b * NP + m.id[j];
                const ulonglong2* pr = (const ulonglong2*)(pf_raw + (size_t)gp * DIM);
                unsigned long long a0 = 0ull, a1 = 0ull;
#pragma unroll
                for (int i = 0; i < 16; i++) {
                    ulonglong2 pv = pr[i];
                    fma2(a0, q2[2 * i], pv.x);
                    fma2(a1, q2[2 * i + 1], pv.y);
                }
                const float f = f2sum(add2(a0, a1));
                n0 += (pts[gp * 3 + 0] - vx) * f;
                n1 += (pts[gp * 3 + 1] - vy) * f;
                n2 += (pts[gp * 3 + 2] - vz) * f;
                den += f;
            }
            const float invd = 1.0f / den;
            const float f0 = n0 * invd, f1 = n1 * invd, f2v = n2 * invd;
            g_flow[qg * 3 + 0] = f0;
            g_flow[qg * 3 + 1] = f1;
            g_flow[qg * 3 + 2] = f2v;
            out[qg * 4 + 0] = f0;
            out[qg * 4 + 1] = f1;
            out[qg * 4 + 2] = f2v;
            out[qg * 4 + 3] = g_vm[qg];
        }
    } else {
        // ================= stage 2 scan =================
        const int sb = blockIdx.x - S1_BLOCKS;
        const int b = sb >> 6;
        const int cnt = g_invis_cnt[b];
        const int base = (sb & 63) * 32;
        if (base >= cnt) return;
        const int vcnt = g_vis_cnt[b];

        const int qslot = base + lane;
        const int qi = g_invis_list[b * NV + min(qslot, cnt - 1)];
        const int qg = b * NV + qi;

        unsigned long long q2[32];
        {
            const ulonglong2* qr = (const ulonglong2*)(vf_raw + (size_t)qg * DIM);
#pragma unroll
            for (int i = 0; i < 16; i++) {
                ulonglong2 t2 = qr[i];
                q2[2 * i] = t2.x;
                q2[2 * i + 1] = t2.y;
            }
        }
        int* skeyw = &midx[8 * w][0];  // staging; midx rewritten only after scan

        const float* vfU = g_vf_unit + (size_t)b * NV * DIM;
        const int* vlist = g_vis_list + b * NV;

        const int ntiles = (vcnt + 15) >> 4;
        const int tpw = (ntiles + 3) >> 2;
        const int t0 = w * tpw;
        const int t1 = min(ntiles, t0 + tpw);

        for (int tt = t0; tt < t1; tt++) {
            const int keyBase = tt * 16;
            if (lane < 16) skeyw[lane] = vlist[min(keyBase + lane, vcnt - 1)];
            __syncwarp();
#pragma unroll
            for (int i = 0; i < 8; i++) {
                const int e = lane + i * 32;
                const int kk = e >> 4;
                const int dd = e & 15;
                const int row = skeyw[kk];
                tile[w][kk][dd] = ((const ulonglong2*)(vfU + (size_t)row * DIM))[dd];
            }
            __syncwarp();
            scan_tile(tile[w], q2, t, 0, skeyw, vcnt - keyBase);
            __syncwarp();
        }
        tk_flush(t);

#pragma unroll
        for (int j = 0; j < 8; j++) {
            mval[w * 8 + j][lane] = t.v[j];
            midx[w * 8 + j][lane] = t.id[j];
        }
        __syncthreads();

        if (w == 0) {
            TopK m;
            tk_init(m);
            for (int c = 0; c < 32; c++) tk_push(m, mval[c][lane], midx[c][lane]);
            tk_flush(m);
            if (qslot < cnt) {
#pragma unroll
                for (int j = 0; j < 8; j++) g_s2idx[qg * 8 + j] = m.id[j];
            }
        }
    }
}

// ---------------- epilogue: invisible flow from stage2 neighbors ----------------
__global__ __launch_bounds__(256) void epilogue_kernel(
    const float* __restrict__ vf_raw, float* __restrict__ out) {
    const int b = blockIdx.y;
    const int cnt = g_invis_cnt[b];
    const int w = threadIdx.x >> 5;
    const int lane = threadIdx.x & 31;
    const int qslot = blockIdx.x * 8 + w;
    if (qslot >= cnt) return;
    const int qi = g_invis_list[b * NV + qslot];
    const int qg = b * NV + qi;

    float n0 = 0.f, n1 = 0.f, n2 = 0.f, den = 0.f;
    if (lane < 8) {
        const int gv = b * NV + g_s2idx[qg * 8 + lane];
        const float4* qr = (const float4*)(vf_raw + (size_t)qg * DIM);
        const float4* kr = (const float4*)(vf_raw + (size_t)gv * DIM);
        float f0 = 0.f, f1 = 0.f, f2 = 0.f, f3 = 0.f;
#pragma unroll
        for (int i = 0; i < 16; i++) {
            const float4 qv = qr[i];
            const float4 kv = kr[i];
            f0 += qv.x * kv.x;
            f1 += qv.y * kv.y;
            f2 += qv.z * kv.z;
            f3 += qv.w * kv.w;
        }
        const float f = (f0 + f1) + (f2 + f3);
        n0 = g_flow[gv * 3 + 0] * f;
        n1 = g_flow[gv * 3 + 1] * f;
        n2 = g_flow[gv * 3 + 2] * f;
        den = f;
    }
#pragma unroll
    for (int o = 4; o > 0; o >>= 1) {
        n0 += __shfl_down_sync(0xffffffffu, n0, o);
        n1 += __shfl_down_sync(0xffffffffu, n1, o);
        n2 += __shfl_down_sync(0xffffffffu, n2, o);
        den += __shfl_down_sync(0xffffffffu, den, o);
    }
    if (lane == 0) {
        const float invd = 1.0f / den;
        out[qg * 4 + 0] = n0 * invd;
        out[qg * 4 + 1] = n1 * invd;
        out[qg * 4 + 2] = n2 * invd;
        out[qg * 4 + 3] = g_vm[qg];
    }
}

// ---------------- launch ----------------
extern "C" void kernel_launch(void* const* d_in, const int* in_sizes, int n_in,
                              void* d_out, int out_size) {
    const float* vtx = (const float*)d_in[0];
    const float* pts = (const float*)d_in[1];
    const float* vf = (const float*)d_in[2];
    const float* pf = (const float*)d_in[3];
    const float* vml = (const float*)d_in[4];
    float* out = (float*)d_out;

    vm_kernel<<<BATCH, 256>>>(vml);
    const int rows = BATCH * (NV + NP);
    norm_kernel<<<(rows * 32) / 256, 256>>>(vf, pf);
    fused_kernel<<<S1_BLOCKS + S2_BLOCKS, 128>>>(vtx, pts, vf, pf, out);
    epilogue_kernel<<<dim3(256, BATCH), 256>>>(vf, out);
}

// round 11
// speedup vs baseline: 1.0903x; 1.0903x over previous
#include <cuda_runtime.h>
#include <math.h>

#define BATCH 8
#define NV 2048
#define NP 4096
#define DIM 64
#define S1_BLOCKS 512
#define S2_BLOCKS 512

// ---------------- scratch (device globals; no allocation) ----------------
__device__ float g_pf_unit[BATCH * NP * DIM];
__device__ float g_vf_unit[BATCH * NV * DIM];
__device__ float g_vm[BATCH * NV];
__device__ float g_flow[BATCH * NV * 3];
__device__ int   g_invis_list[BATCH * NV];
__device__ int   g_vis_list[BATCH * NV];
__device__ int   g_invis_cnt[BATCH];
__device__ int   g_vis_cnt[BATCH];
__device__ int   g_s2idx[BATCH * NV * 8];

// ---------------- f32x2 helpers ----------------
__device__ __forceinline__ void fma2(unsigned long long& d, unsigned long long a,
                                     unsigned long long b) {
    asm("fma.rn.f32x2 %0, %1, %2, %0;" : "+l"(d) : "l"(a), "l"(b));
}
__device__ __forceinline__ unsigned long long add2(unsigned long long a, unsigned long long b) {
    unsigned long long d;
    asm("add.rn.f32x2 %0, %1, %2;" : "=l"(d) : "l"(a), "l"(b));
    return d;
}
__device__ __forceinline__ float f2sum(unsigned long long a) {
    return __uint_as_float((unsigned)a) + __uint_as_float((unsigned)(a >> 32));
}

// ---------------- cp.async helpers ----------------
__device__ __forceinline__ void cp16(void* smem_dst, const void* gsrc) {
    unsigned s = (unsigned)__cvta_generic_to_shared(smem_dst);
    asm volatile("cp.async.cg.shared.global [%0], [%1], 16;" ::"r"(s), "l"(gsrc)
                 : "memory");
}
__device__ __forceinline__ void cp_commit() {
    asm volatile("cp.async.commit_group;" ::: "memory");
}
__device__ __forceinline__ void cp_wait1() {
    asm volatile("cp.async.wait_group 1;" ::: "memory");
}
__device__ __forceinline__ void cp_wait0() {
    asm volatile("cp.async.wait_group 0;" ::: "memory");
}

// ---------------- branchless sorted insert (R5 scheme, measured best) ----------------
__device__ __forceinline__ void topk_insert(float (&v)[8], int (&id)[8], float s, int sid,
                                            bool c) {
    v[0] = c ? s : v[0];
    id[0] = c ? sid : id[0];
#pragma unroll
    for (int j = 0; j < 7; j++) {
        const bool g = v[j] > v[j + 1];
        const float lo = fminf(v[j], v[j + 1]);
        const float hi = fmaxf(v[j], v[j + 1]);
        const int tlo = g ? id[j + 1] : id[j];
        const int thi = g ? id[j] : id[j + 1];
        v[j] = lo;
        v[j + 1] = hi;
        id[j] = tlo;
        id[j + 1] = thi;
    }
}

// ---------------- kernel A: vm + visibility compaction ----------------
__global__ void vm_kernel(const float* __restrict__ logits) {
    const int b = blockIdx.x;
    __shared__ float sv[NV];
    __shared__ float smin[256];
    __shared__ float smax[256];
    __shared__ int c_inv, c_vis;
    float lmin = 1e30f, lmax = -1e30f;
    for (int i = threadIdx.x; i < NV; i += 256) {
        float s = 1.0f / (1.0f + expf(-logits[b * NV + i]));
        sv[i] = s;
        lmin = fminf(lmin, s);
        lmax = fmaxf(lmax, s);
    }
    smin[threadIdx.x] = lmin;
    smax[threadIdx.x] = lmax;
    if (threadIdx.x == 0) { c_inv = 0; c_vis = 0; }
    __syncthreads();
    for (int off = 128; off > 0; off >>= 1) {
        if (threadIdx.x < off) {
            smin[threadIdx.x] = fminf(smin[threadIdx.x], smin[threadIdx.x + off]);
            smax[threadIdx.x] = fmaxf(smax[threadIdx.x], smax[threadIdx.x + off]);
        }
        __syncthreads();
    }
    const float mn = smin[0];
    const float inv = 1.0f / (smax[0] - mn);
    for (int i = threadIdx.x; i < NV; i += 256) {
        float v = (sv[i] - mn) * inv;
        g_vm[b * NV + i] = v;
        if (v >= 0.5f) {
            int p = atomicAdd(&c_vis, 1);
            g_vis_list[b * NV + p] = i;
        } else {
            int p = atomicAdd(&c_inv, 1);
            g_invis_list[b * NV + p] = i;
        }
    }
    __syncthreads();
    if (threadIdx.x == 0) {
        g_vis_cnt[b] = c_vis;
        g_invis_cnt[b] = c_inv;
    }
}

// ---------------- kernel B: unit-normalize key features ----------------
__global__ void norm_kernel(const float* __restrict__ vf, const float* __restrict__ pf) {
    const int gw = (blockIdx.x * blockDim.x + threadIdx.x) >> 5;
    const int lane = threadIdx.x & 31;
    const int totalRows = BATCH * NV + BATCH * NP;
    if (gw >= totalRows) return;
    const float* src;
    float* dst;
    if (gw < BATCH * NV) {
        src = vf + (size_t)gw * DIM;
        dst = g_vf_unit + (size_t)gw * DIM;
    } else {
        const int r = gw - BATCH * NV;
        src = pf + (size_t)r * DIM;
        dst = g_pf_unit + (size_t)r * DIM;
    }
    float2 v = ((const float2*)src)[lane];
    float ss = v.x * v.x + v.y * v.y;
#pragma unroll
    for (int o = 16; o > 0; o >>= 1) ss += __shfl_xor_sync(0xffffffffu, ss, o);
    const float inv = 1.0f / fmaxf(sqrtf(ss), 1e-12f);
    float2 o2;
    o2.x = v.x * inv;
    o2.y = v.y * inv;
    ((float2*)dst)[lane] = o2;
}

// dot of 2 keys against the lane's query
__device__ __forceinline__ float2 dot2(const ulonglong2 (*tw)[16],
                                       const unsigned long long (&q2)[32], int k) {
    unsigned long long a0 = 0ull, a1 = 0ull, b0 = 0ull, b1 = 0ull;
#pragma unroll
    for (int d = 0; d < 16; d++) {
        const ulonglong2 kva = tw[k][d];
        const ulonglong2 kvb = tw[k + 1][d];
        fma2(a0, q2[2 * d], kva.x);
        fma2(a1, q2[2 * d + 1], kva.y);
        fma2(b0, q2[2 * d], kvb.x);
        fma2(b1, q2[2 * d + 1], kvb.y);
    }
    float2 r;
    r.x = f2sum(add2(a0, a1));
    r.y = f2sum(add2(b0, b1));
    return r;
}

// ---------------- fused kernel: stage1 (full) + stage2 KNN scan ----------------
__global__ __launch_bounds__(128, 4) void fused_kernel(
    const float* __restrict__ vtx, const float* __restrict__ pts,
    const float* __restrict__ vf_raw, const float* __restrict__ pf_raw,
    float* __restrict__ out) {
    const int tid = threadIdx.x;
    const int w = tid >> 5;
    const int lane = tid & 31;

    __shared__ ulonglong2 tile[4][2][16][16];  // 32 KB double-buffered
    __shared__ float mval[32][32];             //  4 KB
    __shared__ int midx[32][32];               //  4 KB

    float v[8];
    int id[8];
#pragma unroll
    for (int j = 0; j < 8; j++) { v[j] = -1e30f; id[j] = -1; }

    if (blockIdx.x < S1_BLOCKS) {
        // ================= stage 1 =================
        const int qg = blockIdx.x * 32 + lane;
        const int b = qg >> 11;

        unsigned long long q2[32];
        {
            const ulonglong2* qr = (const ulonglong2*)(vf_raw + (size_t)qg * DIM);
#pragma unroll
            for (int i = 0; i < 16; i++) {
                ulonglong2 t2 = qr[i];
                q2[2 * i] = t2.x;
                q2[2 * i + 1] = t2.y;
            }
        }

        const ulonglong2* pfU = (const ulonglong2*)(g_pf_unit + (size_t)b * NP * DIM);
        const int chunkBase = w * 1024;

        // prologue: issue tile 0 into buffer 0
        {
            const ulonglong2* src = pfU + (size_t)chunkBase * 16;
            ulonglong2* dstT = &tile[w][0][0][0];
#pragma unroll
            for (int i = 0; i < 8; i++) cp16(dstT + lane + i * 32, src + lane + i * 32);
            cp_commit();
        }

        int buf = 0;
        for (int tt = 0; tt < 64; tt++) {
            const int keyBase = chunkBase + tt * 16;
            if (tt + 1 < 64) {
                const ulonglong2* src = pfU + (size_t)(keyBase + 16) * 16;
                ulonglong2* dstT = &tile[w][buf ^ 1][0][0];
#pragma unroll
                for (int i = 0; i < 8; i++) cp16(dstT + lane + i * 32, src + lane + i * 32);
                cp_commit();
                cp_wait1();
            } else {
                cp_wait0();
            }
            __syncwarp();
#pragma unroll
            for (int k = 0; k < 16; k += 2) {
                const float2 s2 = dot2(tile[w][buf], q2, k);
                const bool cA = s2.x > v[0];
                const bool cB = s2.y > v[0];
                if (__ballot_sync(0xffffffffu, cA | cB)) {
                    topk_insert(v, id, s2.x, keyBase + k, cA);
                    topk_insert(v, id, s2.y, keyBase + k + 1, s2.y > v[0]);
                }
            }
            __syncwarp();
            buf ^= 1;
        }

#pragma unroll
        for (int j = 0; j < 8; j++) {
            mval[w * 8 + j][lane] = v[j];
            midx[w * 8 + j][lane] = id[j];
        }
        __syncthreads();

        if (w == 0) {
            float bv[8];
            int bi[8];
#pragma unroll
            for (int j = 0; j < 8; j++) { bv[j] = -1e30f; bi[j] = -1; }
            for (int c = 0; c < 32; c++) {
                const float s = mval[c][lane];
                const bool cc = s > bv[0];
                if (__ballot_sync(0xffffffffu, cc)) topk_insert(bv, bi, s, midx[c][lane], cc);
            }
            const float vx = vtx[qg * 3 + 0];
            const float vy = vtx[qg * 3 + 1];
            const float vz = vtx[qg * 3 + 2];
            float n0 = 0.f, n1 = 0.f, n2 = 0.f, den = 0.f;
#pragma unroll
            for (int j = 0; j < 8; j++) {
                const int gp = b * NP + bi[j];
                const ulonglong2* pr = (const ulonglong2*)(pf_raw + (size_t)gp * DIM);
                unsigned long long a0 = 0ull, a1 = 0ull;
#pragma unroll
                for (int i = 0; i < 16; i++) {
                    ulonglong2 pv = pr[i];
                    fma2(a0, q2[2 * i], pv.x);
                    fma2(a1, q2[2 * i + 1], pv.y);
                }
                const float f = f2sum(add2(a0, a1));
                n0 += (pts[gp * 3 + 0] - vx) * f;
                n1 += (pts[gp * 3 + 1] - vy) * f;
                n2 += (pts[gp * 3 + 2] - vz) * f;
                den += f;
            }
            const float invd = 1.0f / den;
            const float f0 = n0 * invd, f1 = n1 * invd, f2v = n2 * invd;
            g_flow[qg * 3 + 0] = f0;
            g_flow[qg * 3 + 1] = f1;
            g_flow[qg * 3 + 2] = f2v;
            out[qg * 4 + 0] = f0;
            out[qg * 4 + 1] = f1;
            out[qg * 4 + 2] = f2v;
            out[qg * 4 + 3] = g_vm[qg];
        }
    } else {
        // ================= stage 2 scan =================
        const int sb = blockIdx.x - S1_BLOCKS;
        const int b = sb >> 6;
        const int cnt = g_invis_cnt[b];
        const int base = (sb & 63) * 32;
        if (base >= cnt) return;
        const int vcnt = g_vis_cnt[b];

        const int qslot = base + lane;
        const int qi = g_invis_list[b * NV + min(qslot, cnt - 1)];
        const int qg = b * NV + qi;

        unsigned long long q2[32];
        {
            const ulonglong2* qr = (const ulonglong2*)(vf_raw + (size_t)qg * DIM);
#pragma unroll
            for (int i = 0; i < 16; i++) {
                ulonglong2 t2 = qr[i];
                q2[2 * i] = t2.x;
                q2[2 * i + 1] = t2.y;
            }
        }

        const float* vfU = g_vf_unit + (size_t)b * NV * DIM;
        const int* vlist = g_vis_list + b * NV;

        const int ntiles = (vcnt + 15) >> 4;
        const int tpw = (ntiles + 3) >> 2;
        const int t0 = w * tpw;
        const int t1 = min(ntiles, t0 + tpw);

        if (t0 < t1) {
            // prologue: ids + issue for tile t0
            int vidCur = vlist[min(t0 * 16 + (lane & 15), vcnt - 1)];
            {
                ulonglong2* dstT = &tile[w][0][0][0];
#pragma unroll
                for (int i = 0; i < 8; i++) {
                    const int e = lane + i * 32;
                    const int kk = e >> 4;
                    const int dd = e & 15;
                    const int row = __shfl_sync(0xffffffffu, vidCur, kk);
                    cp16(dstT + e, (const ulonglong2*)(vfU + (size_t)row * DIM) + dd);
                }
                cp_commit();
            }
            int buf = 0;
            for (int tt = t0; tt < t1; tt++) {
                const int keyBase = tt * 16;
                int vidNext = vidCur;
                if (tt + 1 < t1) {
                    vidNext = vlist[min((tt + 1) * 16 + (lane & 15), vcnt - 1)];
                    ulonglong2* dstT = &tile[w][buf ^ 1][0][0];
#pragma unroll
                    for (int i = 0; i < 8; i++) {
                        const int e = lane + i * 32;
                        const int kk = e >> 4;
                        const int dd = e & 15;
                        const int row = __shfl_sync(0xffffffffu, vidNext, kk);
                        cp16(dstT + e, (const ulonglong2*)(vfU + (size_t)row * DIM) + dd);
                    }
                    cp_commit();
                    cp_wait1();
                } else {
                    cp_wait0();
                }
                __syncwarp();
                const int validLimit = vcnt - keyBase;
#pragma unroll
                for (int k = 0; k < 16; k += 2) {
                    float2 s2 = dot2(tile[w][buf], q2, k);
                    s2.x = (k < validLimit) ? s2.x : -1e30f;
                    s2.y = (k + 1 < validLimit) ? s2.y : -1e30f;
                    const int idA = __shfl_sync(0xffffffffu, vidCur, k);
                    const int idB = __shfl_sync(0xffffffffu, vidCur, k + 1);
                    const bool cA = s2.x > v[0];
                    const bool cB = s2.y > v[0];
                    if (__ballot_sync(0xffffffffu, cA | cB)) {
                        topk_insert(v, id, s2.x, idA, cA);
                        topk_insert(v, id, s2.y, idB, s2.y > v[0]);
                    }
                }
                __syncwarp();
                vidCur = vidNext;
                buf ^= 1;
            }
        }

#pragma unroll
        for (int j = 0; j < 8; j++) {
            mval[w * 8 + j][lane] = v[j];
            midx[w * 8 + j][lane] = id[j];
        }
        __syncthreads();

        if (w == 0) {
            float bv[8];
            int bi[8];
#pragma unroll
            for (int j = 0; j < 8; j++) { bv[j] = -1e30f; bi[j] = -1; }
            for (int c = 0; c < 32; c++) {
                const float s = mval[c][lane];
                const bool cc = s > bv[0];
                if (__ballot_sync(0xffffffffu, cc)) topk_insert(bv, bi, s, midx[c][lane], cc);
            }
            if (qslot < cnt) {
#pragma unroll
                for (int j = 0; j < 8; j++) g_s2idx[qg * 8 + j] = bi[j];
            }
        }
    }
}

// ---------------- epilogue: invisible flow from stage2 neighbors ----------------
__global__ __launch_bounds__(256) void epilogue_kernel(
    const float* __restrict__ vf_raw, float* __restrict__ out) {
    const int b = blockIdx.y;
    const int cnt = g_invis_cnt[b];
    const int w = threadIdx.x >> 5;
    const int lane = threadIdx.x & 31;
    const int qslot = blockIdx.x * 8 + w;
    if (qslot >= cnt) return;
    const int qi = g_invis_list[b * NV + qslot];
    const int qg = b * NV + qi;

    float n0 = 0.f, n1 = 0.f, n2 = 0.f, den = 0.f;
    if (lane < 8) {
        const int gv = b * NV + g_s2idx[qg * 8 + lane];
        const float4* qr = (const float4*)(vf_raw + (size_t)qg * DIM);
        const float4* kr = (const float4*)(vf_raw + (size_t)gv * DIM);
        float f0 = 0.f, f1 = 0.f, f2 = 0.f, f3 = 0.f;
#pragma unroll
        for (int i = 0; i < 16; i++) {
            const float4 qv = qr[i];
            const float4 kv = kr[i];
            f0 += qv.x * kv.x;
            f1 += qv.y * kv.y;
            f2 += qv.z * kv.z;
            f3 += qv.w * kv.w;
        }
        const float f = (f0 + f1) + (f2 + f3);
        n0 = g_flow[gv * 3 + 0] * f;
        n1 = g_flow[gv * 3 + 1] * f;
        n2 = g_flow[gv * 3 + 2] * f;
        den = f;
    }
#pragma unroll
    for (int o = 4; o > 0; o >>= 1) {
        n0 += __shfl_down_sync(0xffffffffu, n0, o);
        n1 += __shfl_down_sync(0xffffffffu, n1, o);
        n2 += __shfl_down_sync(0xffffffffu, n2, o);
        den += __shfl_down_sync(0xffffffffu, den, o);
    }
    if (lane == 0) {
        const float invd = 1.0f / den;
        out[qg * 4 + 0] = n0 * invd;
        out[qg * 4 + 1] = n1 * invd;
        out[qg * 4 + 2] = n2 * invd;
        out[qg * 4 + 3] = g_vm[qg];
    }
}

// ---------------- launch ----------------
extern "C" void kernel_launch(void* const* d_in, const int* in_sizes, int n_in,
                              void* d_out, int out_size) {
    const float* vtx = (const float*)d_in[0];
    const float* pts = (const float*)d_in[1];
    const float* vf = (const float*)d_in[2];
    const float* pf = (const float*)d_in[3];
    const float* vml = (const float*)d_in[4];
    float* out = (float*)d_out;

    vm_kernel<<<BATCH, 256>>>(vml);
    const int rows = BATCH * (NV + NP);
    norm_kernel<<<(rows * 32) / 256, 256>>>(vf, pf);
    fused_kernel<<<S1_BLOCKS + S2_BLOCKS, 128>>>(vtx, pts, vf, pf, out);
    epilogue_kernel<<<dim3(256, BATCH), 256>>>(vf, out);
}

// round 14
// speedup vs baseline: 1.1979x; 1.0987x over previous
#include <cuda_runtime.h>
#include <math.h>

#define BATCH 8
#define NV 2048
#define NP 4096
#define DIM 64
#define S1_BLOCKS 512
#define S2_BLOCKS 512

// ---------------- scratch (device globals; no allocation) ----------------
__device__ float g_pf_unit[BATCH * NP * DIM];
__device__ float g_vf_unit[BATCH * NV * DIM];
__device__ float g_vm[BATCH * NV];
__device__ float g_flow[BATCH * NV * 3];
__device__ int   g_invis_list[BATCH * NV];
__device__ int   g_vis_list[BATCH * NV];
__device__ int   g_invis_cnt[BATCH];
__device__ int   g_vis_cnt[BATCH];
__device__ int   g_s2idx[BATCH * NV * 8];

// ---------------- f32x2 helpers ----------------
__device__ __forceinline__ void fma2(unsigned long long& d, unsigned long long a,
                                     unsigned long long b) {
    asm("fma.rn.f32x2 %0, %1, %2, %0;" : "+l"(d) : "l"(a), "l"(b));
}
__device__ __forceinline__ unsigned long long add2(unsigned long long a, unsigned long long b) {
    unsigned long long d;
    asm("add.rn.f32x2 %0, %1, %2;" : "=l"(d) : "l"(a), "l"(b));
    return d;
}
__device__ __forceinline__ float f2sum(unsigned long long a) {
    return __uint_as_float((unsigned)a) + __uint_as_float((unsigned)(a >> 32));
}

// ---------------- cp.async helpers ----------------
__device__ __forceinline__ void cp16(void* smem_dst, const void* gsrc) {
    unsigned s = (unsigned)__cvta_generic_to_shared(smem_dst);
    asm volatile("cp.async.cg.shared.global [%0], [%1], 16;" ::"r"(s), "l"(gsrc)
                 : "memory");
}
__device__ __forceinline__ void cp_commit() {
    asm volatile("cp.async.commit_group;" ::: "memory");
}
__device__ __forceinline__ void cp_wait1() {
    asm volatile("cp.async.wait_group 1;" ::: "memory");
}
__device__ __forceinline__ void cp_wait0() {
    asm volatile("cp.async.wait_group 0;" ::: "memory");
}

// ---------------- branchless sorted insert ----------------
__device__ __forceinline__ void topk_insert(float (&v)[8], int (&id)[8], float s, int sid,
                                            bool c) {
    v[0] = c ? s : v[0];
    id[0] = c ? sid : id[0];
#pragma unroll
    for (int j = 0; j < 7; j++) {
        const bool g = v[j] > v[j + 1];
        const float lo = fminf(v[j], v[j + 1]);
        const float hi = fmaxf(v[j], v[j + 1]);
        const int tlo = g ? id[j + 1] : id[j];
        const int thi = g ? id[j] : id[j + 1];
        v[j] = lo;
        v[j + 1] = hi;
        id[j] = tlo;
        id[j + 1] = thi;
    }
}

// process 4 scores: unconditional max-insert + rare residual branch (exact top-8)
__device__ __forceinline__ void topk_push4(float (&v)[8], int (&id)[8], float s0, float s1,
                                           float s2, float s3, int i0, int i1, int i2,
                                           int i3) {
    // max of 4, earliest index on ties (strict >)
    float smax = s0;
    int jmax = 0, imax = i0;
    bool g;
    g = s1 > smax; smax = g ? s1 : smax; jmax = g ? 1 : jmax; imax = g ? i1 : imax;
    g = s2 > smax; smax = g ? s2 : smax; jmax = g ? 2 : jmax; imax = g ? i2 : imax;
    g = s3 > smax; smax = g ? s3 : smax; jmax = g ? 3 : jmax; imax = g ? i3 : imax;
    topk_insert(v, id, smax, imax, smax > v[0]);
    // residuals (rare): any non-max score still above the (updated) threshold
    const bool r0 = (jmax != 0) & (s0 > v[0]);
    const bool r1 = (jmax != 1) & (s1 > v[0]);
    const bool r2 = (jmax != 2) & (s2 > v[0]);
    const bool r3 = (jmax != 3) & (s3 > v[0]);
    if (__ballot_sync(0xffffffffu, r0 | r1 | r2 | r3)) {
        topk_insert(v, id, s0, i0, (jmax != 0) & (s0 > v[0]));
        topk_insert(v, id, s1, i1, (jmax != 1) & (s1 > v[0]));
        topk_insert(v, id, s2, i2, (jmax != 2) & (s2 > v[0]));
        topk_insert(v, id, s3, i3, (jmax != 3) & (s3 > v[0]));
    }
}

// ---------------- kernel A: vm + visibility compaction ----------------
__global__ void vm_kernel(const float* __restrict__ logits) {
    const int b = blockIdx.x;
    __shared__ float sv[NV];
    __shared__ float smin[256];
    __shared__ float smax_s[256];
    __shared__ int c_inv, c_vis;
    float lmin = 1e30f, lmax = -1e30f;
    for (int i = threadIdx.x; i < NV; i += 256) {
        float s = 1.0f / (1.0f + expf(-logits[b * NV + i]));
        sv[i] = s;
        lmin = fminf(lmin, s);
        lmax = fmaxf(lmax, s);
    }
    smin[threadIdx.x] = lmin;
    smax_s[threadIdx.x] = lmax;
    if (threadIdx.x == 0) { c_inv = 0; c_vis = 0; }
    __syncthreads();
    for (int off = 128; off > 0; off >>= 1) {
        if (threadIdx.x < off) {
            smin[threadIdx.x] = fminf(smin[threadIdx.x], smin[threadIdx.x + off]);
            smax_s[threadIdx.x] = fmaxf(smax_s[threadIdx.x], smax_s[threadIdx.x + off]);
        }
        __syncthreads();
    }
    const float mn = smin[0];
    const float inv = 1.0f / (smax_s[0] - mn);
    for (int i = threadIdx.x; i < NV; i += 256) {
        float v = (sv[i] - mn) * inv;
        g_vm[b * NV + i] = v;
        if (v >= 0.5f) {
            int p = atomicAdd(&c_vis, 1);
            g_vis_list[b * NV + p] = i;
        } else {
            int p = atomicAdd(&c_inv, 1);
            g_invis_list[b * NV + p] = i;
        }
    }
    __syncthreads();
    if (threadIdx.x == 0) {
        g_vis_cnt[b] = c_vis;
        g_invis_cnt[b] = c_inv;
    }
}

// ---------------- kernel B: unit-normalize key features ----------------
__global__ void norm_kernel(const float* __restrict__ vf, const float* __restrict__ pf) {
    const int gw = (blockIdx.x * blockDim.x + threadIdx.x) >> 5;
    const int lane = threadIdx.x & 31;
    const int totalRows = BATCH * NV + BATCH * NP;
    if (gw >= totalRows) return;
    const float* src;
    float* dst;
    if (gw < BATCH * NV) {
        src = vf + (size_t)gw * DIM;
        dst = g_vf_unit + (size_t)gw * DIM;
    } else {
        const int r = gw - BATCH * NV;
        src = pf + (size_t)r * DIM;
        dst = g_pf_unit + (size_t)r * DIM;
    }
    float2 v = ((const float2*)src)[lane];
    float ss = v.x * v.x + v.y * v.y;
#pragma unroll
    for (int o = 16; o > 0; o >>= 1) ss += __shfl_xor_sync(0xffffffffu, ss, o);
    const float inv = 1.0f / fmaxf(sqrtf(ss), 1e-12f);
    float2 o2;
    o2.x = v.x * inv;
    o2.y = v.y * inv;
    ((float2*)dst)[lane] = o2;
}

// dot of 4 keys against the lane's query
__device__ __forceinline__ float4 dot4(const ulonglong2 (*tw)[16],
                                       const unsigned long long (&q2)[32], int k) {
    unsigned long long a0 = 0ull, a1 = 0ull, b0 = 0ull, b1 = 0ull;
    unsigned long long c0 = 0ull, c1 = 0ull, d0 = 0ull, d1 = 0ull;
#pragma unroll
    for (int d = 0; d < 16; d++) {
        const ulonglong2 kva = tw[k][d];
        const ulonglong2 kvb = tw[k + 1][d];
        const ulonglong2 kvc = tw[k + 2][d];
        const ulonglong2 kvd = tw[k + 3][d];
        fma2(a0, q2[2 * d], kva.x);
        fma2(a1, q2[2 * d + 1], kva.y);
        fma2(b0, q2[2 * d], kvb.x);
        fma2(b1, q2[2 * d + 1], kvb.y);
        fma2(c0, q2[2 * d], kvc.x);
        fma2(c1, q2[2 * d + 1], kvc.y);
        fma2(d0, q2[2 * d], kvd.x);
        fma2(d1, q2[2 * d + 1], kvd.y);
    }
    float4 r;
    r.x = f2sum(add2(a0, a1));
    r.y = f2sum(add2(b0, b1));
    r.z = f2sum(add2(c0, c1));
    r.w = f2sum(add2(d0, d1));
    return r;
}

// ---------------- fused kernel: stage1 (full) + stage2 KNN scan ----------------
__global__ __launch_bounds__(128, 4) void fused_kernel(
    const float* __restrict__ vtx, const float* __restrict__ pts,
    const float* __restrict__ vf_raw, const float* __restrict__ pf_raw,
    float* __restrict__ out) {
    const int tid = threadIdx.x;
    const int w = tid >> 5;
    const int lane = tid & 31;

    __shared__ ulonglong2 tile[4][2][16][16];  // 32 KB double-buffered
    __shared__ float mval[32][32];             //  4 KB
    __shared__ int midx[32][32];               //  4 KB

    float v[8];
    int id[8];
#pragma unroll
    for (int j = 0; j < 8; j++) { v[j] = -1e30f; id[j] = -1; }

    if (blockIdx.x < S1_BLOCKS) {
        // ================= stage 1 =================
        const int qg = blockIdx.x * 32 + lane;
        const int b = qg >> 11;

        unsigned long long q2[32];
        {
            const ulonglong2* qr = (const ulonglong2*)(vf_raw + (size_t)qg * DIM);
#pragma unroll
            for (int i = 0; i < 16; i++) {
                ulonglong2 t2 = qr[i];
                q2[2 * i] = t2.x;
                q2[2 * i + 1] = t2.y;
            }
        }

        const ulonglong2* pfU = (const ulonglong2*)(g_pf_unit + (size_t)b * NP * DIM);
        const int chunkBase = w * 1024;

        // prologue: issue tile 0 into buffer 0
        {
            const ulonglong2* src = pfU + (size_t)chunkBase * 16;
            ulonglong2* dstT = &tile[w][0][0][0];
#pragma unroll
            for (int i = 0; i < 8; i++) cp16(dstT + lane + i * 32, src + lane + i * 32);
            cp_commit();
        }

        int buf = 0;
        for (int tt = 0; tt < 64; tt++) {
            const int keyBase = chunkBase + tt * 16;
            if (tt + 1 < 64) {
                const ulonglong2* src = pfU + (size_t)(keyBase + 16) * 16;
                ulonglong2* dstT = &tile[w][buf ^ 1][0][0];
#pragma unroll
                for (int i = 0; i < 8; i++) cp16(dstT + lane + i * 32, src + lane + i * 32);
                cp_commit();
                cp_wait1();
            } else {
                cp_wait0();
            }
            __syncwarp();
#pragma unroll
            for (int k = 0; k < 16; k += 4) {
                const float4 s4 = dot4(tile[w][buf], q2, k);
                topk_push4(v, id, s4.x, s4.y, s4.z, s4.w, keyBase + k, keyBase + k + 1,
                           keyBase + k + 2, keyBase + k + 3);
            }
            __syncwarp();
            buf ^= 1;
        }

#pragma unroll
        for (int j = 0; j < 8; j++) {
            mval[w * 8 + j][lane] = v[j];
            midx[w * 8 + j][lane] = id[j];
        }
        __syncthreads();

        if (w == 0) {
            float bv[8];
            int bi[8];
#pragma unroll
            for (int j = 0; j < 8; j++) { bv[j] = -1e30f; bi[j] = -1; }
            for (int c = 0; c < 32; c++) {
                const float s = mval[c][lane];
                topk_insert(bv, bi, s, midx[c][lane], s > bv[0]);
            }
            const float vx = vtx[qg * 3 + 0];
            const float vy = vtx[qg * 3 + 1];
            const float vz = vtx[qg * 3 + 2];
            float n0 = 0.f, n1 = 0.f, n2 = 0.f, den = 0.f;
#pragma unroll
            for (int j = 0; j < 8; j++) {
                const int gp = b * NP + bi[j];
                const ulonglong2* pr = (const ulonglong2*)(pf_raw + (size_t)gp * DIM);
                unsigned long long a0 = 0ull, a1 = 0ull;
#pragma unroll
                for (int i = 0; i < 16; i++) {
                    ulonglong2 pv = pr[i];
                    fma2(a0, q2[2 * i], pv.x);
                    fma2(a1, q2[2 * i + 1], pv.y);
                }
                const float f = f2sum(add2(a0, a1));
                n0 += (pts[gp * 3 + 0] - vx) * f;
                n1 += (pts[gp * 3 + 1] - vy) * f;
                n2 += (pts[gp * 3 + 2] - vz) * f;
                den += f;
            }
            const float invd = 1.0f / den;
            const float f0 = n0 * invd, f1 = n1 * invd, f2v = n2 * invd;
            g_flow[qg * 3 + 0] = f0;
            g_flow[qg * 3 + 1] = f1;
            g_flow[qg * 3 + 2] = f2v;
            out[qg * 4 + 0] = f0;
            out[qg * 4 + 1] = f1;
            out[qg * 4 + 2] = f2v;
            out[qg * 4 + 3] = g_vm[qg];
        }
    } else {
        // ================= stage 2 scan =================
        const int sb = blockIdx.x - S1_BLOCKS;
        const int b = sb >> 6;
        const int cnt = g_invis_cnt[b];
        const int base = (sb & 63) * 32;
        if (base >= cnt) return;
        const int vcnt = g_vis_cnt[b];

        const int qslot = base + lane;
        const int qi = g_invis_list[b * NV + min(qslot, cnt - 1)];
        const int qg = b * NV + qi;

        unsigned long long q2[32];
        {
            const ulonglong2* qr = (const ulonglong2*)(vf_raw + (size_t)qg * DIM);
#pragma unroll
            for (int i = 0; i < 16; i++) {
                ulonglong2 t2 = qr[i];
                q2[2 * i] = t2.x;
                q2[2 * i + 1] = t2.y;
            }
        }

        const float* vfU = g_vf_unit + (size_t)b * NV * DIM;
        const int* vlist = g_vis_list + b * NV;

        const int ntiles = (vcnt + 15) >> 4;
        const int tpw = (ntiles + 3) >> 2;
        const int t0 = w * tpw;
        const int t1 = min(ntiles, t0 + tpw);

        if (t0 < t1) {
            int vidCur = vlist[min(t0 * 16 + (lane & 15), vcnt - 1)];
            {
                ulonglong2* dstT = &tile[w][0][0][0];
#pragma unroll
                for (int i = 0; i < 8; i++) {
                    const int e = lane + i * 32;
                    const int kk = e >> 4;
                    const int dd = e & 15;
                    const int row = __shfl_sync(0xffffffffu, vidCur, kk);
                    cp16(dstT + e, (const ulonglong2*)(vfU + (size_t)row * DIM) + dd);
                }
                cp_commit();
            }
            int buf = 0;
            for (int tt = t0; tt < t1; tt++) {
                const int keyBase = tt * 16;
                int vidNext = vidCur;
                if (tt + 1 < t1) {
                    vidNext = vlist[min((tt + 1) * 16 + (lane & 15), vcnt - 1)];
                    ulonglong2* dstT = &tile[w][buf ^ 1][0][0];
#pragma unroll
                    for (int i = 0; i < 8; i++) {
                        const int e = lane + i * 32;
                        const int kk = e >> 4;
                        const int dd = e & 15;
                        const int row = __shfl_sync(0xffffffffu, vidNext, kk);
                        cp16(dstT + e, (const ulonglong2*)(vfU + (size_t)row * DIM) + dd);
                    }
                    cp_commit();
                    cp_wait1();
                } else {
                    cp_wait0();
                }
                __syncwarp();
                const int validLimit = vcnt - keyBase;
#pragma unroll
                for (int k = 0; k < 16; k += 4) {
                    float4 s4 = dot4(tile[w][buf], q2, k);
                    s4.x = (k < validLimit) ? s4.x : -1e30f;
                    s4.y = (k + 1 < validLimit) ? s4.y : -1e30f;
                    s4.z = (k + 2 < validLimit) ? s4.z : -1e30f;
                    s4.w = (k + 3 < validLimit) ? s4.w : -1e30f;
                    const int iA = __shfl_sync(0xffffffffu, vidCur, k);
                    const int iB = __shfl_sync(0xffffffffu, vidCur, k + 1);
                    const int iC = __shfl_sync(0xffffffffu, vidCur, k + 2);
                    const int iD = __shfl_sync(0xffffffffu, vidCur, k + 3);
                    topk_push4(v, id, s4.x, s4.y, s4.z, s4.w, iA, iB, iC, iD);
                }
                __syncwarp();
                vidCur = vidNext;
                buf ^= 1;
            }
        }

#pragma unroll
        for (int j = 0; j < 8; j++) {
            mval[w * 8 + j][lane] = v[j];
            midx[w * 8 + j][lane] = id[j];
        }
        __syncthreads();

        if (w == 0) {
            float bv[8];
            int bi[8];
#pragma unroll
            for (int j = 0; j < 8; j++) { bv[j] = -1e30f; bi[j] = -1; }
            for (int c = 0; c < 32; c++) {
                const float s = mval[c][lane];
                topk_insert(bv, bi, s, midx[c][lane], s > bv[0]);
            }
            if (qslot < cnt) {
#pragma unroll
                for (int j = 0; j < 8; j++) g_s2idx[qg * 8 + j] = bi[j];
            }
        }
    }
}

// ---------------- epilogue: invisible flow from stage2 neighbors ----------------
__global__ __launch_bounds__(256) void epilogue_kernel(
    const float* __restrict__ vf_raw, float* __restrict__ out) {
    const int b = blockIdx.y;
    const int cnt = g_invis_cnt[b];
    const int w = threadIdx.x >> 5;
    const int lane = threadIdx.x & 31;
    const int qslot = blockIdx.x * 8 + w;
    if (qslot >= cnt) return;
    const int qi = g_invis_list[b * NV + qslot];
    const int qg = b * NV + qi;

    float n0 = 0.f, n1 = 0.f, n2 = 0.f, den = 0.f;
    if (lane < 8) {
        const int gv = b * NV + g_s2idx[qg * 8 + lane];
        const float4* qr = (const float4*)(vf_raw + (size_t)qg * DIM);
        const float4* kr = (const float4*)(vf_raw + (size_t)gv * DIM);
        float f0 = 0.f, f1 = 0.f, f2 = 0.f, f3 = 0.f;
#pragma unroll
        for (int i = 0; i < 16; i++) {
            const float4 qv = qr[i];
            const float4 kv = kr[i];
            f0 += qv.x * kv.x;
            f1 += qv.y * kv.y;
            f2 += qv.z * kv.z;
            f3 += qv.w * kv.w;
        }
        const float f = (f0 + f1) + (f2 + f3);
        n0 = g_flow[gv * 3 + 0] * f;
        n1 = g_flow[gv * 3 + 1] * f;
        n2 = g_flow[gv * 3 + 2] * f;
        den = f;
    }
#pragma unroll
    for (int o = 4; o > 0; o >>= 1) {
        n0 += __shfl_down_sync(0xffffffffu, n0, o);
        n1 += __shfl_down_sync(0xffffffffu, n1, o);
        n2 += __shfl_down_sync(0xffffffffu, n2, o);
        den += __shfl_down_sync(0xffffffffu, den, o);
    }
    if (lane == 0) {
        const float invd = 1.0f / den;
        out[qg * 4 + 0] = n0 * invd;
        out[qg * 4 + 1] = n1 * invd;
        out[qg * 4 + 2] = n2 * invd;
        out[qg * 4 + 3] = g_vm[qg];
    }
}

// ---------------- launch ----------------
extern "C" void kernel_launch(void* const* d_in, const int* in_sizes, int n_in,
                              void* d_out, int out_size) {
    const float* vtx = (const float*)d_in[0];
    const float* pts = (const float*)d_in[1];
    const float* vf = (const float*)d_in[2];
    const float* pf = (const float*)d_in[3];
    const float* vml = (const float*)d_in[4];
    float* out = (float*)d_out;

    vm_kernel<<<BATCH, 256>>>(vml);
    const int rows = BATCH * (NV + NP);
    norm_kernel<<<(rows * 32) / 256, 256>>>(vf, pf);
    fused_kernel<<<S1_BLOCKS + S2_BLOCKS, 128>>>(vtx, pts, vf, pf, out);
    epilogue_kernel<<<dim3(256, BATCH), 256>>>(vf, out);
}

// round 15
// speedup vs baseline: 1.2145x; 1.0138x over previous
#include <cuda_runtime.h>
#include <math.h>

#define BATCH 8
#define NV 2048
#define NP 4096
#define DIM 64
#define S1_ITEMS 512
#define TOTAL_ITEMS 1024
#define PERSIST_BLOCKS 608  // 4 per SM x 152 SMs (GB300)

// ---------------- scratch (device globals; no allocation) ----------------
__device__ float g_pf_unit[BATCH * NP * DIM];
__device__ float g_vf_unit[BATCH * NV * DIM];
__device__ float g_vm[BATCH * NV];
__device__ float g_flow[BATCH * NV * 3];
__device__ int   g_invis_list[BATCH * NV];
__device__ int   g_vis_list[BATCH * NV];
__device__ int   g_invis_cnt[BATCH];
__device__ int   g_vis_cnt[BATCH];
__device__ int   g_s2idx[BATCH * NV * 8];
__device__ int   g_work;   // persistent work counter (zeroed each replay by vm_kernel)

// ---------------- f32x2 helpers ----------------
__device__ __forceinline__ void fma2(unsigned long long& d, unsigned long long a,
                                     unsigned long long b) {
    asm("fma.rn.f32x2 %0, %1, %2, %0;" : "+l"(d) : "l"(a), "l"(b));
}
__device__ __forceinline__ unsigned long long add2(unsigned long long a, unsigned long long b) {
    unsigned long long d;
    asm("add.rn.f32x2 %0, %1, %2;" : "=l"(d) : "l"(a), "l"(b));
    return d;
}
__device__ __forceinline__ float f2sum(unsigned long long a) {
    return __uint_as_float((unsigned)a) + __uint_as_float((unsigned)(a >> 32));
}

// ---------------- cp.async helpers ----------------
__device__ __forceinline__ void cp16(void* smem_dst, const void* gsrc) {
    unsigned s = (unsigned)__cvta_generic_to_shared(smem_dst);
    asm volatile("cp.async.cg.shared.global [%0], [%1], 16;" ::"r"(s), "l"(gsrc)
                 : "memory");
}
__device__ __forceinline__ void cp_commit() {
    asm volatile("cp.async.commit_group;" ::: "memory");
}
__device__ __forceinline__ void cp_wait1() {
    asm volatile("cp.async.wait_group 1;" ::: "memory");
}
__device__ __forceinline__ void cp_wait0() {
    asm volatile("cp.async.wait_group 0;" ::: "memory");
}

// ---------------- branchless sorted insert ----------------
__device__ __forceinline__ void topk_insert(float (&v)[8], int (&id)[8], float s, int sid,
                                            bool c) {
    v[0] = c ? s : v[0];
    id[0] = c ? sid : id[0];
#pragma unroll
    for (int j = 0; j < 7; j++) {
        const bool g = v[j] > v[j + 1];
        const float lo = fminf(v[j], v[j + 1]);
        const float hi = fmaxf(v[j], v[j + 1]);
        const int tlo = g ? id[j + 1] : id[j];
        const int thi = g ? id[j] : id[j + 1];
        v[j] = lo;
        v[j + 1] = hi;
        id[j] = tlo;
        id[j + 1] = thi;
    }
}

// process 4 scores: unconditional max-insert + rare residual branch (exact top-8)
__device__ __forceinline__ void topk_push4(float (&v)[8], int (&id)[8], float s0, float s1,
                                           float s2, float s3, int i0, int i1, int i2,
                                           int i3) {
    float smax = s0;
    int jmax = 0, imax = i0;
    bool g;
    g = s1 > smax; smax = g ? s1 : smax; jmax = g ? 1 : jmax; imax = g ? i1 : imax;
    g = s2 > smax; smax = g ? s2 : smax; jmax = g ? 2 : jmax; imax = g ? i2 : imax;
    g = s3 > smax; smax = g ? s3 : smax; jmax = g ? 3 : jmax; imax = g ? i3 : imax;
    topk_insert(v, id, smax, imax, smax > v[0]);
    const bool r0 = (jmax != 0) & (s0 > v[0]);
    const bool r1 = (jmax != 1) & (s1 > v[0]);
    const bool r2 = (jmax != 2) & (s2 > v[0]);
    const bool r3 = (jmax != 3) & (s3 > v[0]);
    if (__ballot_sync(0xffffffffu, r0 | r1 | r2 | r3)) {
        topk_insert(v, id, s0, i0, (jmax != 0) & (s0 > v[0]));
        topk_insert(v, id, s1, i1, (jmax != 1) & (s1 > v[0]));
        topk_insert(v, id, s2, i2, (jmax != 2) & (s2 > v[0]));
        topk_insert(v, id, s3, i3, (jmax != 3) & (s3 > v[0]));
    }
}

// ---------------- kernel A: vm + visibility compaction (+ work counter reset) ----------------
__global__ void vm_kernel(const float* __restrict__ logits) {
    const int b = blockIdx.x;
    if (b == 0 && threadIdx.x == 0) g_work = 0;  // reset persistent queue each replay
    __shared__ float sv[NV];
    __shared__ float smin[256];
    __shared__ float smax_s[256];
    __shared__ int c_inv, c_vis;
    float lmin = 1e30f, lmax = -1e30f;
    for (int i = threadIdx.x; i < NV; i += 256) {
        float s = 1.0f / (1.0f + expf(-logits[b * NV + i]));
        sv[i] = s;
        lmin = fminf(lmin, s);
        lmax = fmaxf(lmax, s);
    }
    smin[threadIdx.x] = lmin;
    smax_s[threadIdx.x] = lmax;
    if (threadIdx.x == 0) { c_inv = 0; c_vis = 0; }
    __syncthreads();
    for (int off = 128; off > 0; off >>= 1) {
        if (threadIdx.x < off) {
            smin[threadIdx.x] = fminf(smin[threadIdx.x], smin[threadIdx.x + off]);
            smax_s[threadIdx.x] = fmaxf(smax_s[threadIdx.x], smax_s[threadIdx.x + off]);
        }
        __syncthreads();
    }
    const float mn = smin[0];
    const float inv = 1.0f / (smax_s[0] - mn);
    for (int i = threadIdx.x; i < NV; i += 256) {
        float v = (sv[i] - mn) * inv;
        g_vm[b * NV + i] = v;
        if (v >= 0.5f) {
            int p = atomicAdd(&c_vis, 1);
            g_vis_list[b * NV + p] = i;
        } else {
            int p = atomicAdd(&c_inv, 1);
            g_invis_list[b * NV + p] = i;
        }
    }
    __syncthreads();
    if (threadIdx.x == 0) {
        g_vis_cnt[b] = c_vis;
        g_invis_cnt[b] = c_inv;
    }
}

// ---------------- kernel B: unit-normalize key features ----------------
__global__ void norm_kernel(const float* __restrict__ vf, const float* __restrict__ pf) {
    const int gw = (blockIdx.x * blockDim.x + threadIdx.x) >> 5;
    const int lane = threadIdx.x & 31;
    const int totalRows = BATCH * NV + BATCH * NP;
    if (gw >= totalRows) return;
    const float* src;
    float* dst;
    if (gw < BATCH * NV) {
        src = vf + (size_t)gw * DIM;
        dst = g_vf_unit + (size_t)gw * DIM;
    } else {
        const int r = gw - BATCH * NV;
        src = pf + (size_t)r * DIM;
        dst = g_pf_unit + (size_t)r * DIM;
    }
    float2 v = ((const float2*)src)[lane];
    float ss = v.x * v.x + v.y * v.y;
#pragma unroll
    for (int o = 16; o > 0; o >>= 1) ss += __shfl_xor_sync(0xffffffffu, ss, o);
    const float inv = 1.0f / fmaxf(sqrtf(ss), 1e-12f);
    float2 o2;
    o2.x = v.x * inv;
    o2.y = v.y * inv;
    ((float2*)dst)[lane] = o2;
}

// dot of 4 keys against the lane's query
__device__ __forceinline__ float4 dot4(const ulonglong2 (*tw)[16],
                                       const unsigned long long (&q2)[32], int k) {
    unsigned long long a0 = 0ull, a1 = 0ull, b0 = 0ull, b1 = 0ull;
    unsigned long long c0 = 0ull, c1 = 0ull, d0 = 0ull, d1 = 0ull;
#pragma unroll
    for (int d = 0; d < 16; d++) {
        const ulonglong2 kva = tw[k][d];
        const ulonglong2 kvb = tw[k + 1][d];
        const ulonglong2 kvc = tw[k + 2][d];
        const ulonglong2 kvd = tw[k + 3][d];
        fma2(a0, q2[2 * d], kva.x);
        fma2(a1, q2[2 * d + 1], kva.y);
        fma2(b0, q2[2 * d], kvb.x);
        fma2(b1, q2[2 * d + 1], kvb.y);
        fma2(c0, q2[2 * d], kvc.x);
        fma2(c1, q2[2 * d + 1], kvc.y);
        fma2(d0, q2[2 * d], kvd.x);
        fma2(d1, q2[2 * d + 1], kvd.y);
    }
    float4 r;
    r.x = f2sum(add2(a0, a1));
    r.y = f2sum(add2(b0, b1));
    r.z = f2sum(add2(c0, c1));
    r.w = f2sum(add2(d0, d1));
    return r;
}

// ---------------- fused persistent kernel: stage1 + stage2 scan ----------------
__global__ __launch_bounds__(128, 4) void fused_kernel(
    const float* __restrict__ vtx, const float* __restrict__ pts,
    const float* __restrict__ vf_raw, const float* __restrict__ pf_raw,
    float* __restrict__ out) {
    const int tid = threadIdx.x;
    const int w = tid >> 5;
    const int lane = tid & 31;

    __shared__ ulonglong2 tile[4][2][16][16];  // 32 KB double-buffered
    __shared__ float mval[32][32];             //  4 KB
    __shared__ int midx[32][32];               //  4 KB
    __shared__ int s_item;

    for (;;) {
        if (tid == 0) s_item = atomicAdd(&g_work, 1);
        __syncthreads();
        const int item = s_item;
        if (item >= TOTAL_ITEMS) break;

        float v[8];
        int id[8];
#pragma unroll
        for (int j = 0; j < 8; j++) { v[j] = -1e30f; id[j] = -1; }

        if (item < S1_ITEMS) {
            // ================= stage 1 =================
            const int qg = item * 32 + lane;
            const int b = qg >> 11;

            unsigned long long q2[32];
            {
                const ulonglong2* qr = (const ulonglong2*)(vf_raw + (size_t)qg * DIM);
#pragma unroll
                for (int i = 0; i < 16; i++) {
                    ulonglong2 t2 = qr[i];
                    q2[2 * i] = t2.x;
                    q2[2 * i + 1] = t2.y;
                }
            }

            const ulonglong2* pfU = (const ulonglong2*)(g_pf_unit + (size_t)b * NP * DIM);
            const int chunkBase = w * 1024;

            {
                const ulonglong2* src = pfU + (size_t)chunkBase * 16;
                ulonglong2* dstT = &tile[w][0][0][0];
#pragma unroll
                for (int i = 0; i < 8; i++) cp16(dstT + lane + i * 32, src + lane + i * 32);
                cp_commit();
            }

            int buf = 0;
            for (int tt = 0; tt < 64; tt++) {
                const int keyBase = chunkBase + tt * 16;
                if (tt + 1 < 64) {
                    const ulonglong2* src = pfU + (size_t)(keyBase + 16) * 16;
                    ulonglong2* dstT = &tile[w][buf ^ 1][0][0];
#pragma unroll
                    for (int i = 0; i < 8; i++)
                        cp16(dstT + lane + i * 32, src + lane + i * 32);
                    cp_commit();
                    cp_wait1();
                } else {
                    cp_wait0();
                }
                __syncwarp();
#pragma unroll
                for (int k = 0; k < 16; k += 4) {
                    const float4 s4 = dot4(tile[w][buf], q2, k);
                    topk_push4(v, id, s4.x, s4.y, s4.z, s4.w, keyBase + k, keyBase + k + 1,
                               keyBase + k + 2, keyBase + k + 3);
                }
                __syncwarp();
                buf ^= 1;
            }

#pragma unroll
            for (int j = 0; j < 8; j++) {
                mval[w * 8 + j][lane] = v[j];
                midx[w * 8 + j][lane] = id[j];
            }
            __syncthreads();

            if (w == 0) {
                float bv[8];
                int bi[8];
#pragma unroll
                for (int j = 0; j < 8; j++) { bv[j] = -1e30f; bi[j] = -1; }
                for (int c = 0; c < 32; c++) {
                    const float s = mval[c][lane];
                    topk_insert(bv, bi, s, midx[c][lane], s > bv[0]);
                }
                const float vx = vtx[qg * 3 + 0];
                const float vy = vtx[qg * 3 + 1];
                const float vz = vtx[qg * 3 + 2];
                float n0 = 0.f, n1 = 0.f, n2 = 0.f, den = 0.f;
#pragma unroll
                for (int j = 0; j < 8; j++) {
                    const int gp = b * NP + bi[j];
                    const ulonglong2* pr = (const ulonglong2*)(pf_raw + (size_t)gp * DIM);
                    unsigned long long a0 = 0ull, a1 = 0ull;
#pragma unroll
                    for (int i = 0; i < 16; i++) {
                        ulonglong2 pv = pr[i];
                        fma2(a0, q2[2 * i], pv.x);
                        fma2(a1, q2[2 * i + 1], pv.y);
                    }
                    const float f = f2sum(add2(a0, a1));
                    n0 += (pts[gp * 3 + 0] - vx) * f;
                    n1 += (pts[gp * 3 + 1] - vy) * f;
                    n2 += (pts[gp * 3 + 2] - vz) * f;
                    den += f;
                }
                const float invd = 1.0f / den;
                const float f0 = n0 * invd, f1 = n1 * invd, f2v = n2 * invd;
                g_flow[qg * 3 + 0] = f0;
                g_flow[qg * 3 + 1] = f1;
                g_flow[qg * 3 + 2] = f2v;
                out[qg * 4 + 0] = f0;
                out[qg * 4 + 1] = f1;
                out[qg * 4 + 2] = f2v;
                out[qg * 4 + 3] = g_vm[qg];
            }
        } else {
            // ================= stage 2 scan =================
            const int sb = item - S1_ITEMS;
            const int b = sb >> 6;
            const int cnt = g_invis_cnt[b];
            const int base = (sb & 63) * 32;
            if (base < cnt) {
                const int vcnt = g_vis_cnt[b];

                const int qslot = base + lane;
                const int qi = g_invis_list[b * NV + min(qslot, cnt - 1)];
                const int qg = b * NV + qi;

                unsigned long long q2[32];
                {
                    const ulonglong2* qr = (const ulonglong2*)(vf_raw + (size_t)qg * DIM);
#pragma unroll
                    for (int i = 0; i < 16; i++) {
                        ulonglong2 t2 = qr[i];
                        q2[2 * i] = t2.x;
                        q2[2 * i + 1] = t2.y;
                    }
                }

                const float* vfU = g_vf_unit + (size_t)b * NV * DIM;
                const int* vlist = g_vis_list + b * NV;

                const int ntiles = (vcnt + 15) >> 4;
                const int tpw = (ntiles + 3) >> 2;
                const int t0 = w * tpw;
                const int t1 = min(ntiles, t0 + tpw);

                if (t0 < t1) {
                    int vidCur = vlist[min(t0 * 16 + (lane & 15), vcnt - 1)];
                    {
                        ulonglong2* dstT = &tile[w][0][0][0];
#pragma unroll
                        for (int i = 0; i < 8; i++) {
                            const int e = lane + i * 32;
                            const int kk = e >> 4;
                            const int dd = e & 15;
                            const int row = __shfl_sync(0xffffffffu, vidCur, kk);
                            cp16(dstT + e, (const ulonglong2*)(vfU + (size_t)row * DIM) + dd);
                        }
                        cp_commit();
                    }
                    int buf = 0;
                    for (int tt = t0; tt < t1; tt++) {
                        const int keyBase = tt * 16;
                        int vidNext = vidCur;
                        if (tt + 1 < t1) {
                            vidNext = vlist[min((tt + 1) * 16 + (lane & 15), vcnt - 1)];
                            ulonglong2* dstT = &tile[w][buf ^ 1][0][0];
#pragma unroll
                            for (int i = 0; i < 8; i++) {
                                const int e = lane + i * 32;
                                const int kk = e >> 4;
                                const int dd = e & 15;
                                const int row = __shfl_sync(0xffffffffu, vidNext, kk);
                                cp16(dstT + e,
                                     (const ulonglong2*)(vfU + (size_t)row * DIM) + dd);
                            }
                            cp_commit();
                            cp_wait1();
                        } else {
                            cp_wait0();
                        }
                        __syncwarp();
                        const int validLimit = vcnt - keyBase;
#pragma unroll
                        for (int k = 0; k < 16; k += 4) {
                            float4 s4 = dot4(tile[w][buf], q2, k);
                            s4.x = (k < validLimit) ? s4.x : -1e30f;
                            s4.y = (k + 1 < validLimit) ? s4.y : -1e30f;
                            s4.z = (k + 2 < validLimit) ? s4.z : -1e30f;
                            s4.w = (k + 3 < validLimit) ? s4.w : -1e30f;
                            const int iA = __shfl_sync(0xffffffffu, vidCur, k);
                            const int iB = __shfl_sync(0xffffffffu, vidCur, k + 1);
                            const int iC = __shfl_sync(0xffffffffu, vidCur, k + 2);
                            const int iD = __shfl_sync(0xffffffffu, vidCur, k + 3);
                            topk_push4(v, id, s4.x, s4.y, s4.z, s4.w, iA, iB, iC, iD);
                        }
                        __syncwarp();
                        vidCur = vidNext;
                        buf ^= 1;
                    }
                }

#pragma unroll
                for (int j = 0; j < 8; j++) {
                    mval[w * 8 + j][lane] = v[j];
                    midx[w * 8 + j][lane] = id[j];
                }
                __syncthreads();

                if (w == 0) {
                    float bv[8];
                    int bi[8];
#pragma unroll
                    for (int j = 0; j < 8; j++) { bv[j] = -1e30f; bi[j] = -1; }
                    for (int c = 0; c < 32; c++) {
                        const float s = mval[c][lane];
                        topk_insert(bv, bi, s, midx[c][lane], s > bv[0]);
                    }
                    if (qslot < cnt) {
#pragma unroll
                        for (int j = 0; j < 8; j++) g_s2idx[qg * 8 + j] = bi[j];
                    }
                }
            }
        }
        __syncthreads();  // shared (tile/mval/midx/s_item) reuse barrier
    }
}

// ---------------- epilogue: invisible flow from stage2 neighbors ----------------
__global__ __launch_bounds__(256) void epilogue_kernel(
    const float* __restrict__ vf_raw, float* __restrict__ out) {
    const int b = blockIdx.y;
    const int cnt = g_invis_cnt[b];
    const int w = threadIdx.x >> 5;
    const int lane = threadIdx.x & 31;
    const int qslot = blockIdx.x * 8 + w;
    if (qslot >= cnt) return;
    const int qi = g_invis_list[b * NV + qslot];
    const int qg = b * NV + qi;

    float n0 = 0.f, n1 = 0.f, n2 = 0.f, den = 0.f;
    if (lane < 8) {
        const int gv = b * NV + g_s2idx[qg * 8 + lane];
        const float4* qr = (const float4*)(vf_raw + (size_t)qg * DIM);
        const float4* kr = (const float4*)(vf_raw + (size_t)gv * DIM);
        float f0 = 0.f, f1 = 0.f, f2 = 0.f, f3 = 0.f;
#pragma unroll
        for (int i = 0; i < 16; i++) {
            const float4 qv = qr[i];
            const float4 kv = kr[i];
            f0 += qv.x * kv.x;
            f1 += qv.y * kv.y;
            f2 += qv.z * kv.z;
            f3 += qv.w * kv.w;
        }
        const float f = (f0 + f1) + (f2 + f3);
        n0 = g_flow[gv * 3 + 0] * f;
        n1 = g_flow[gv * 3 + 1] * f;
        n2 = g_flow[gv * 3 + 2] * f;
        den = f;
    }
#pragma unroll
    for (int o = 4; o > 0; o >>= 1) {
        n0 += __shfl_down_sync(0xffffffffu, n0, o);
        n1 += __shfl_down_sync(0xffffffffu, n1, o);
        n2 += __shfl_down_sync(0xffffffffu, n2, o);
        den += __shfl_down_sync(0xffffffffu, den, o);
    }
    if (lane == 0) {
        const float invd = 1.0f / den;
        out[qg * 4 + 0] = n0 * invd;
        out[qg * 4 + 1] = n1 * invd;
        out[qg * 4 + 2] = n2 * invd;
        out[qg * 4 + 3] = g_vm[qg];
    }
}

// ---------------- launch ----------------
extern "C" void kernel_launch(void* const* d_in, const int* in_sizes, int n_in,
                              void* d_out, int out_size) {
    const float* vtx = (const float*)d_in[0];
    const float* pts = (const float*)d_in[1];
    const float* vf = (const float*)d_in[2];
    const float* pf = (const float*)d_in[3];
    const float* vml = (const float*)d_in[4];
    float* out = (float*)d_out;

    vm_kernel<<<BATCH, 256>>>(vml);
    const int rows = BATCH * (NV + NP);
    norm_kernel<<<(rows * 32) / 256, 256>>>(vf, pf);
    fused_kernel<<<PERSIST_BLOCKS, 128>>>(vtx, pts, vf, pf, out);
    epilogue_kernel<<<dim3(256, BATCH), 256>>>(vf, out);
}